// round 2
// baseline (speedup 1.0000x reference)
#include <cuda_runtime.h>
#include <cstdint>

#define FULLMASK 0xffffffffu

static constexpr int BB   = 16;
static constexpr int NN   = 4096;
static constexpr int CC   = 64;
static constexpr int MM   = 1024;
static constexpr int KNN  = 32;

typedef unsigned long long u64;

// --------------------------------------------------------------------------
// Scratch (device globals; no runtime allocation allowed)
// --------------------------------------------------------------------------
__device__ int   g_cidx[BB * MM];
__device__ int   g_nidx[BB * MM * KNN];
__device__ float g_h1f[(size_t)BB * NN * 64];   // W1_feat @ features, [b][n][64]

// --------------------------------------------------------------------------
// Packed f32x2 helpers (IEEE rn, bit-identical to scalar rn ops)
// --------------------------------------------------------------------------
__device__ __forceinline__ u64 pk2(float lo, float hi) {
    u64 r; asm("mov.b64 %0,{%1,%2};" : "=l"(r) : "f"(lo), "f"(hi)); return r;
}
__device__ __forceinline__ void upk2(u64 v, float& lo, float& hi) {
    asm("mov.b64 {%0,%1},%2;" : "=f"(lo), "=f"(hi) : "l"(v));
}
__device__ __forceinline__ u64 add2(u64 a, u64 b) {
    u64 r; asm("add.rn.f32x2 %0,%1,%2;" : "=l"(r) : "l"(a), "l"(b)); return r;
}
__device__ __forceinline__ u64 mul2(u64 a, u64 b) {
    u64 r; asm("mul.rn.f32x2 %0,%1,%2;" : "=l"(r) : "l"(a), "l"(b)); return r;
}
__device__ __forceinline__ u64 fma2p(u64 a, u64 b, u64 c) {
    u64 r; asm("fma.rn.f32x2 %0,%1,%2,%3;" : "=l"(r) : "l"(a), "l"(b), "l"(c)); return r;
}
__device__ __forceinline__ void lds128(u64& a, u64& b, unsigned addr) {
    asm volatile("ld.shared.v2.u64 {%0,%1},[%2];" : "=l"(a), "=l"(b) : "r"(addr));
}

// --------------------------------------------------------------------------
// Kernel 1: blocks 0..15 -> FPS (one block per batch, points in registers)
//           blocks 16..271 -> h1f precompute (W1[:,3:67] @ features)
// dynamic smem: 16KB (FPS: cidx cache; h1f: weight tile)
// --------------------------------------------------------------------------
__global__ void __launch_bounds__(256) k_fps_h1f(
    const float* __restrict__ points,
    const float* __restrict__ features,
    const float* __restrict__ w1,
    float* __restrict__ d_out)
{
    extern __shared__ float smf[];
    const int t = threadIdx.x;

    if (blockIdx.x < BB) {
        // ------------------------- FPS -------------------------
        __shared__ float bwv[8];
        __shared__ int   bwi[8];
        int* scidx = (int*)smf;                // 1024 ints

        const int b = blockIdx.x;
        const float* px = points + (size_t)b * 3 * NN;

        u64 x2[8], y2[8], z2[8];
        float dl[8], dh[8];
#pragma unroll
        for (int q = 0; q < 8; q++) {
            int pi = (q << 8) + t;             // u64 index; floats 2*pi, 2*pi+1
            x2[q] = ((const u64*)px)[pi];
            y2[q] = ((const u64*)(px + NN))[pi];
            z2[q] = ((const u64*)(px + 2 * NN))[pi];
            dl[q] = 1e10f; dh[q] = 1e10f;
        }
        if (t == 0) { g_cidx[b * MM] = 0; scidx[0] = 0; }
        float lx = px[0], ly = px[NN], lz = px[2 * NN];
        const int lane = t & 31, wid = t >> 5;

        for (int m = 1; m < MM; m++) {
            const u64 nx = pk2(-lx, -lx), ny = pk2(-ly, -ly), nz = pk2(-lz, -lz);
            float bestv = -1.0f; int besti = 0;
#pragma unroll
            for (int q = 0; q < 8; q++) {
                u64 dx = add2(x2[q], nx);
                u64 dy = add2(y2[q], ny);
                u64 dz = add2(z2[q], nz);
                u64 d2 = add2(add2(mul2(dx, dx), mul2(dy, dy)), mul2(dz, dz));
                float a, c; upk2(d2, a, c);
                dl[q] = fminf(dl[q], a);
                dh[q] = fminf(dh[q], c);
                int i0 = (q << 9) + (t << 1);
                if (dl[q] > bestv) { bestv = dl[q]; besti = i0; }
                if (dh[q] > bestv) { bestv = dh[q]; besti = i0 + 1; }
            }
#pragma unroll
            for (int off = 16; off; off >>= 1) {
                float ov = __shfl_xor_sync(FULLMASK, bestv, off);
                int   oi = __shfl_xor_sync(FULLMASK, besti, off);
                if (ov > bestv || (ov == bestv && oi < besti)) { bestv = ov; besti = oi; }
            }
            if (lane == 0) { bwv[wid] = bestv; bwi[wid] = besti; }
            __syncthreads();
            bestv = bwv[0]; besti = bwi[0];
#pragma unroll
            for (int ww = 1; ww < 8; ww++) {
                float ov = bwv[ww]; int oi = bwi[ww];
                if (ov > bestv || (ov == bestv && oi < besti)) { bestv = ov; besti = oi; }
            }
            if (t == 0) { g_cidx[b * MM + m] = besti; scidx[m] = besti; }
            lx = __ldg(px + besti);
            ly = __ldg(px + NN + besti);
            lz = __ldg(px + 2 * NN + besti);
            __syncthreads();                   // protect bwv/bwi for next iter
        }
        __syncthreads();
        // centroid coords output: [B,3,M]
        for (int mm = t; mm < MM; mm += 256) {
            int ii = scidx[mm];
            d_out[(size_t)b * 3 * MM + mm]          = __ldg(px + ii);
            d_out[(size_t)b * 3 * MM + MM + mm]     = __ldg(px + NN + ii);
            d_out[(size_t)b * 3 * MM + 2 * MM + mm] = __ldg(px + 2 * NN + ii);
        }
    } else {
        // ------------------------- h1f precompute -------------------------
        const int job = blockIdx.x - BB;       // 0..255
        const int b   = job >> 4;
        const int n   = ((job & 15) << 8) + t;

        for (int i = t; i < 64 * 64; i += 256) {
            int c = i >> 6, o = i & 63;
            smf[c * 64 + o] = w1[o * 67 + 3 + c];
        }
        __syncthreads();

        u64 acc[32];
#pragma unroll
        for (int k = 0; k < 32; k++) acc[k] = 0ULL;

        const float* fb = features + (size_t)b * CC * NN + n;
        unsigned wbase = (unsigned)__cvta_generic_to_shared(smf);
#pragma unroll
        for (int c = 0; c < 64; c++) {
            float f = fb[c * NN];
            u64 vv = pk2(f, f);
            unsigned addr = wbase + c * 256;
#pragma unroll
            for (int k = 0; k < 16; k++) {
                u64 wa, wb; lds128(wa, wb, addr + k * 16);
                acc[2 * k]     = fma2p(wa, vv, acc[2 * k]);
                acc[2 * k + 1] = fma2p(wb, vv, acc[2 * k + 1]);
            }
        }
        ulonglong2* op = (ulonglong2*)(g_h1f + ((size_t)b * NN + n) * 64);
#pragma unroll
        for (int k = 0; k < 16; k++)
            op[k] = make_ulonglong2(acc[2 * k], acc[2 * k + 1]);
    }
}

// --------------------------------------------------------------------------
// Kernel 2: ball query (warp per centroid, first-K-by-index, register compaction)
// dynamic smem: 48KB exactly (3 coord arrays)
// --------------------------------------------------------------------------
__global__ void __launch_bounds__(256) k_ballquery(const float* __restrict__ points)
{
    extern __shared__ float sm[];
    float* sx = sm;
    float* sy = sm + NN;
    float* sz = sm + 2 * NN;

    const int b = blockIdx.y;
    const float* px = points + (size_t)b * 3 * NN;
    for (int i = threadIdx.x; i < NN; i += 256) {
        sx[i] = px[i];
        sy[i] = px[NN + i];
        sz[i] = px[2 * NN + i];
    }
    __syncthreads();

    const int w = threadIdx.x >> 5, lane = threadIdx.x & 31;
    const int m = blockIdx.x * 8 + w;
    const int ci = g_cidx[b * MM + m];
    const float cx = sx[ci], cy = sy[ci], cz = sz[ci];
    const float c2 = __fadd_rn(__fadd_rn(__fmul_rn(cx, cx), __fmul_rn(cy, cy)),
                               __fmul_rn(cz, cz));

    // matches JAX: f32(0.04 in f64) — NOT 0.2f*0.2f (1 ulp higher)
    const float RR = (float)(0.2 * 0.2);

    int myn = -1;
    int cnt = 0;
    for (int base = 0; base < NN; base += 32) {
        int n = base + lane;
        float xx = sx[n], yy = sy[n], zz = sz[n];
        float p2 = __fadd_rn(__fadd_rn(__fmul_rn(xx, xx), __fmul_rn(yy, yy)),
                             __fmul_rn(zz, zz));
        float dot = __fadd_rn(__fadd_rn(__fmul_rn(cx, xx), __fmul_rn(cy, yy)),
                              __fmul_rn(cz, zz));
        float d2 = __fsub_rn(__fadd_rn(c2, p2), __fmul_rn(2.0f, dot));
        unsigned msk = __ballot_sync(FULLMASK, d2 <= RR);
        int p = __popc(msk);
        if (lane >= cnt && lane < cnt + p) {
            // lane is the (lane - cnt + 1)-th hit of this chunk
            myn = base + (int)__fns(msk, 0, lane - cnt + 1);
        }
        cnt += p;
        if (cnt >= KNN) break;
    }
    int first = __shfl_sync(FULLMASK, myn, 0);   // >=1 hit guaranteed (self)
    if (myn < 0) myn = first;
    g_nidx[((size_t)b * MM + m) * KNN + lane] = myn;
}

// --------------------------------------------------------------------------
// Kernel 3: fused gather + 3-layer MLP (packed f32x2) + max-pool
// warp = centroid, lane = neighbor. dynamic smem: 48KB exactly.
// --------------------------------------------------------------------------
__global__ void __launch_bounds__(256) k_mlp(
    const float* __restrict__ points,
    const float* __restrict__ w1, const float* __restrict__ b1,
    const float* __restrict__ g1, const float* __restrict__ be1,
    const float* __restrict__ w2, const float* __restrict__ b2,
    const float* __restrict__ g2, const float* __restrict__ be2,
    const float* __restrict__ w3, const float* __restrict__ b3,
    const float* __restrict__ g3, const float* __restrict__ be3,
    float* __restrict__ d_out)
{
    extern __shared__ float smf[];     // [0,4096) w2T*s2 ; [4096,12288) w3T*s3
    const int tid = threadIdx.x;
    const float inv = 1.0f / sqrtf(1.0f + 1e-5f);

    for (int i = tid; i < 4096; i += 256) {
        int o = i & 63, c = i >> 6;
        smf[c * 64 + o] = w2[o * 64 + c] * (__ldg(g2 + o) * inv);
    }
    for (int i = tid; i < 8192; i += 256) {
        int o = i & 127, c = i >> 7;
        smf[4096 + c * 128 + o] = w3[o * 64 + c] * (__ldg(g3 + o) * inv);
    }
    __syncthreads();

    const int w = tid >> 5, lane = tid & 31;
    const int b = blockIdx.y;
    const int m = blockIdx.x * 8 + w;
    const int ci = g_cidx[b * MM + m];
    const int n  = g_nidx[((size_t)b * MM + m) * KNN + lane];

    const float* px = points + (size_t)b * 3 * NN;
    const float lx = px[n] - px[ci];
    const float ly = px[NN + n] - px[NN + ci];
    const float lz = px[2 * NN + n] - px[2 * NN + ci];

    const unsigned sb = (unsigned)__cvta_generic_to_shared(smf);

    // ---- layer 1 (feature half pre-gathered; finish with local coords) ----
    float h1[64];
    {
        const float4* hp = (const float4*)(g_h1f + ((size_t)b * NN + n) * 64);
#pragma unroll
        for (int q = 0; q < 16; q++) {
            float4 v = hp[q];
            h1[4 * q] = v.x; h1[4 * q + 1] = v.y; h1[4 * q + 2] = v.z; h1[4 * q + 3] = v.w;
        }
#pragma unroll
        for (int o = 0; o < 64; o++) {
            float raw = h1[o]
                      + __ldg(w1 + o * 67)     * lx
                      + __ldg(w1 + o * 67 + 1) * ly
                      + __ldg(w1 + o * 67 + 2) * lz
                      + __ldg(b1 + o);
            float tv = raw * (__ldg(g1 + o) * inv) + __ldg(be1 + o);
            h1[o] = fmaxf(tv, 0.0f);
        }
    }

    // ---- layer 2 (packed over output pairs) ----
    u64 acc[32];
#pragma unroll
    for (int k = 0; k < 32; k++) acc[k] = 0ULL;
#pragma unroll
    for (int c = 0; c < 64; c++) {
        u64 vv = pk2(h1[c], h1[c]);
        unsigned addr = sb + c * 256;
#pragma unroll
        for (int k = 0; k < 16; k++) {
            u64 wa, wb; lds128(wa, wb, addr + k * 16);
            acc[2 * k]     = fma2p(wa, vv, acc[2 * k]);
            acc[2 * k + 1] = fma2p(wb, vv, acc[2 * k + 1]);
        }
    }
    float h2[64];
#pragma unroll
    for (int k = 0; k < 32; k++) upk2(acc[k], h2[2 * k], h2[2 * k + 1]);
#pragma unroll
    for (int o = 0; o < 64; o++) {
        float b2f = fmaf(__ldg(b2 + o), __ldg(g2 + o) * inv, __ldg(be2 + o));
        h2[o] = fmaxf(h2[o] + b2f, 0.0f);
    }

    // ---- layer 3 (4 chunks of 32 outputs) + warp max-pool ----
    float* ofeat = d_out + (size_t)BB * 3 * MM;
#pragma unroll
    for (int ch = 0; ch < 4; ch++) {
        u64 a2[16];
#pragma unroll
        for (int k = 0; k < 16; k++) a2[k] = 0ULL;
#pragma unroll
        for (int c = 0; c < 64; c++) {
            u64 vv = pk2(h2[c], h2[c]);
            unsigned addr = sb + 16384 + c * 512 + ch * 128;
#pragma unroll
            for (int k = 0; k < 8; k++) {
                u64 wa, wb; lds128(wa, wb, addr + k * 16);
                a2[2 * k]     = fma2p(wa, vv, a2[2 * k]);
                a2[2 * k + 1] = fma2p(wb, vv, a2[2 * k + 1]);
            }
        }
        float v[32];
#pragma unroll
        for (int k = 0; k < 16; k++) upk2(a2[k], v[2 * k], v[2 * k + 1]);

        // exchange-halving butterfly: lane l ends with max over lanes of channel l
#pragma unroll
        for (int off = 16; off >= 1; off >>= 1) {
            bool hi = (lane & off) != 0;
#pragma unroll
            for (int j = 0; j < 16; j++) {
                if (j < off) {
                    float mine = hi ? v[j + off] : v[j];
                    float send = hi ? v[j] : v[j + off];
                    float oth = __shfl_xor_sync(FULLMASK, send, off);
                    v[j] = fmaxf(mine, oth);
                }
            }
        }
        // channel-uniform affine + relu commute with max -> apply once
        const int o = ch * 32 + lane;
        float b3f = fmaf(__ldg(b3 + o), __ldg(g3 + o) * inv, __ldg(be3 + o));
        float r = fmaxf(v[0] + b3f, 0.0f);
        ofeat[((size_t)b * 128 + o) * MM + m] = r;
    }
}

// --------------------------------------------------------------------------
extern "C" void kernel_launch(void* const* d_in, const int* in_sizes, int n_in,
                              void* d_out, int out_size)
{
    const float* points   = (const float*)d_in[0];
    const float* features = (const float*)d_in[1];
    const float* w1  = (const float*)d_in[2];
    const float* b1  = (const float*)d_in[3];
    const float* g1  = (const float*)d_in[4];
    const float* be1 = (const float*)d_in[5];
    const float* w2  = (const float*)d_in[6];
    const float* b2  = (const float*)d_in[7];
    const float* g2  = (const float*)d_in[8];
    const float* be2 = (const float*)d_in[9];
    const float* w3  = (const float*)d_in[10];
    const float* b3  = (const float*)d_in[11];
    const float* g3  = (const float*)d_in[12];
    const float* be3 = (const float*)d_in[13];
    float* out = (float*)d_out;

    // K1: FPS (blocks 0..15) + h1f precompute (blocks 16..271); 16KB dyn smem
    k_fps_h1f<<<BB + 256, 256, 16384>>>(points, features, w1, out);
    // K2: ball query; 48KB dyn smem (no opt-in needed)
    k_ballquery<<<dim3(MM / 8, BB), 256, 3 * NN * 4>>>(points);
    // K3: fused MLP + max-pool; 48KB dyn smem
    k_mlp<<<dim3(MM / 8, BB), 256, 12288 * 4>>>(points,
                                                w1, b1, g1, be1,
                                                w2, b2, g2, be2,
                                                w3, b3, g3, be3, out);
}

// round 3
// speedup vs baseline: 2.0491x; 2.0491x over previous
#include <cuda_runtime.h>
#include <cstdint>

#define FULLMASK 0xffffffffu

static constexpr int BB   = 16;
static constexpr int NN   = 4096;
static constexpr int CC   = 64;
static constexpr int MM   = 1024;
static constexpr int KNN  = 32;

typedef unsigned long long u64;

// --------------------------------------------------------------------------
// Scratch (device globals; no runtime allocation allowed)
// --------------------------------------------------------------------------
__device__ int      g_cidx[BB * MM];
__device__ float    g_h1f[(size_t)BB * NN * 64];   // W1_feat @ features, [b][n][64]
__device__ unsigned g_pairs[BB * MM * KNN];        // packed (b<<22)|(m<<12)|n
__device__ int      g_pcount;

// --------------------------------------------------------------------------
// Packed f32x2 helpers (IEEE rn, bit-identical to scalar rn ops)
// --------------------------------------------------------------------------
__device__ __forceinline__ u64 pk2(float lo, float hi) {
    u64 r; asm("mov.b64 %0,{%1,%2};" : "=l"(r) : "f"(lo), "f"(hi)); return r;
}
__device__ __forceinline__ void upk2(u64 v, float& lo, float& hi) {
    asm("mov.b64 {%0,%1},%2;" : "=f"(lo), "=f"(hi) : "l"(v));
}
__device__ __forceinline__ u64 add2(u64 a, u64 b) {
    u64 r; asm("add.rn.f32x2 %0,%1,%2;" : "=l"(r) : "l"(a), "l"(b)); return r;
}
__device__ __forceinline__ u64 mul2(u64 a, u64 b) {
    u64 r; asm("mul.rn.f32x2 %0,%1,%2;" : "=l"(r) : "l"(a), "l"(b)); return r;
}
__device__ __forceinline__ u64 fma2p(u64 a, u64 b, u64 c) {
    u64 r; asm("fma.rn.f32x2 %0,%1,%2,%3;" : "=l"(r) : "l"(a), "l"(b), "l"(c)); return r;
}
__device__ __forceinline__ void lds128(u64& a, u64& b, unsigned addr) {
    asm volatile("ld.shared.v2.u64 {%0,%1},[%2];" : "=l"(a), "=l"(b) : "r"(addr));
}

// --------------------------------------------------------------------------
// Kernel 1: blocks 0..15 -> FPS; blocks 16..271 -> h1f precompute + out zeroing
// dynamic smem: 16KB
// --------------------------------------------------------------------------
__global__ void __launch_bounds__(256) k_fps_h1f(
    const float* __restrict__ points,
    const float* __restrict__ features,
    const float* __restrict__ w1,
    float* __restrict__ d_out)
{
    extern __shared__ float smf[];
    const int t = threadIdx.x;

    if (blockIdx.x < BB) {
        // ------------------------- FPS -------------------------
        __shared__ u64 sbuf[2][8];
        int* scidx = (int*)smf;                // 1024 ints

        const int b = blockIdx.x;
        const float* px = points + (size_t)b * 3 * NN;

        u64 x2[8], y2[8], z2[8];
        float dl[8], dh[8];
#pragma unroll
        for (int q = 0; q < 8; q++) {
            int pi = (q << 8) + t;
            x2[q] = ((const u64*)px)[pi];
            y2[q] = ((const u64*)(px + NN))[pi];
            z2[q] = ((const u64*)(px + 2 * NN))[pi];
            dl[q] = 1e10f; dh[q] = 1e10f;
        }
        if (t == 0) { g_cidx[b * MM] = 0; scidx[0] = 0; }
        float lx = px[0], ly = px[NN], lz = px[2 * NN];
        const int lane = t & 31, wid = t >> 5;

        for (int m = 1; m < MM; m++) {
            const u64 nx = pk2(-lx, -lx), ny = pk2(-ly, -ly), nz = pk2(-lz, -lz);
            float vq[8];
#pragma unroll
            for (int q = 0; q < 8; q++) {
                u64 dx = add2(x2[q], nx);
                u64 dy = add2(y2[q], ny);
                u64 dz = add2(z2[q], nz);
                u64 d2 = add2(add2(mul2(dx, dx), mul2(dy, dy)), mul2(dz, dz));
                float a, c; upk2(d2, a, c);
                dl[q] = fminf(dl[q], a);
                dh[q] = fminf(dh[q], c);
                vq[q] = fmaxf(dl[q], dh[q]);
            }
            // per-thread max tree
            float vm = fmaxf(fmaxf(fmaxf(vq[0], vq[1]), fmaxf(vq[2], vq[3])),
                             fmaxf(fmaxf(vq[4], vq[5]), fmaxf(vq[6], vq[7])));
            // warp max value (positive f32 -> u32 ordering)
            unsigned bu = __reduce_max_sync(FULLMASK, __float_as_uint(vm));
            // exact min index among matches (same tie-break as jnp.argmax)
            unsigned cand = 0xFFFFFFFFu;
#pragma unroll
            for (int q = 0; q < 8; q++) {
                unsigned i0 = (q << 9) + (t << 1);
                if (__float_as_uint(dl[q]) == bu) cand = min(cand, i0);
                if (__float_as_uint(dh[q]) == bu) cand = min(cand, i0 + 1);
            }
            unsigned wi = __reduce_min_sync(FULLMASK, cand);
            if (lane == 0)
                sbuf[m & 1][wid] = ((u64)bu << 32) | (u64)(~wi);
            __syncthreads();
            u64 best = sbuf[m & 1][0];
#pragma unroll
            for (int w = 1; w < 8; w++) {
                u64 o = sbuf[m & 1][w];
                if (o > best) best = o;
            }
            int besti = (int)(~(unsigned)best);
            if (t == 0) { g_cidx[b * MM + m] = besti; scidx[m] = besti; }
            lx = __ldg(px + besti);
            ly = __ldg(px + NN + besti);
            lz = __ldg(px + 2 * NN + besti);
        }
        __syncthreads();
        // centroid coords output: [B,3,M]
        for (int mm = t; mm < MM; mm += 256) {
            int ii = scidx[mm];
            d_out[(size_t)b * 3 * MM + mm]          = __ldg(px + ii);
            d_out[(size_t)b * 3 * MM + MM + mm]     = __ldg(px + NN + ii);
            d_out[(size_t)b * 3 * MM + 2 * MM + mm] = __ldg(px + 2 * NN + ii);
        }
    } else {
        // ------------- h1f precompute + output zero + pcount reset -------------
        const int job = blockIdx.x - BB;       // 0..255
        const int b   = job >> 4;
        const int n   = ((job & 15) << 8) + t;

        if (job == 0 && t == 0) g_pcount = 0;
        // zero feature output region [BB*128*MM floats]
        {
            float* ofeat = d_out + (size_t)BB * 3 * MM;
            int base = job * 256 + t;          // 0..65535
            for (int r = 0; r < 32; r++)
                ofeat[(size_t)base * 32 + r] = 0.0f;
        }

        for (int i = t; i < 64 * 64; i += 256) {
            int c = i >> 6, o = i & 63;
            smf[c * 64 + o] = w1[o * 67 + 3 + c];
        }
        __syncthreads();

        u64 acc[32];
#pragma unroll
        for (int k = 0; k < 32; k++) acc[k] = 0ULL;

        const float* fb = features + (size_t)b * CC * NN + n;
        unsigned wbase = (unsigned)__cvta_generic_to_shared(smf);
#pragma unroll
        for (int c = 0; c < 64; c++) {
            float f = fb[c * NN];
            u64 vv = pk2(f, f);
            unsigned addr = wbase + c * 256;
#pragma unroll
            for (int k = 0; k < 16; k++) {
                u64 wa, wb; lds128(wa, wb, addr + k * 16);
                acc[2 * k]     = fma2p(wa, vv, acc[2 * k]);
                acc[2 * k + 1] = fma2p(wb, vv, acc[2 * k + 1]);
            }
        }
        ulonglong2* op = (ulonglong2*)(g_h1f + ((size_t)b * NN + n) * 64);
#pragma unroll
        for (int k = 0; k < 16; k++)
            op[k] = make_ulonglong2(acc[2 * k], acc[2 * k + 1]);
    }
}

// --------------------------------------------------------------------------
// Kernel 2: ball query -> compacted distinct-pair list
// dynamic smem: 48KB exactly (3 coord arrays)
// --------------------------------------------------------------------------
__global__ void __launch_bounds__(256) k_ballquery(const float* __restrict__ points)
{
    extern __shared__ float sm[];
    float* sx = sm;
    float* sy = sm + NN;
    float* sz = sm + 2 * NN;

    const int b = blockIdx.y;
    const float* px = points + (size_t)b * 3 * NN;
    for (int i = threadIdx.x; i < NN; i += 256) {
        sx[i] = px[i];
        sy[i] = px[NN + i];
        sz[i] = px[2 * NN + i];
    }
    __syncthreads();

    const int w = threadIdx.x >> 5, lane = threadIdx.x & 31;
    const int m = blockIdx.x * 8 + w;
    const int ci = g_cidx[b * MM + m];
    const float cx = sx[ci], cy = sy[ci], cz = sz[ci];
    const float c2 = __fadd_rn(__fadd_rn(__fmul_rn(cx, cx), __fmul_rn(cy, cy)),
                               __fmul_rn(cz, cz));

    // matches JAX: f32(0.04 in f64) — NOT 0.2f*0.2f (1 ulp higher)
    const float RR = (float)(0.2 * 0.2);

    int myn = -1;
    int cnt = 0;
    for (int base = 0; base < NN; base += 32) {
        int n = base + lane;
        float xx = sx[n], yy = sy[n], zz = sz[n];
        float p2 = __fadd_rn(__fadd_rn(__fmul_rn(xx, xx), __fmul_rn(yy, yy)),
                             __fmul_rn(zz, zz));
        float dot = __fadd_rn(__fadd_rn(__fmul_rn(cx, xx), __fmul_rn(cy, yy)),
                              __fmul_rn(cz, zz));
        float d2 = __fsub_rn(__fadd_rn(c2, p2), __fmul_rn(2.0f, dot));
        unsigned msk = __ballot_sync(FULLMASK, d2 <= RR);
        int p = __popc(msk);
        if (lane >= cnt && lane < cnt + p)
            myn = base + (int)__fns(msk, 0, lane - cnt + 1);
        cnt += p;
        if (cnt >= KNN) break;
    }
    int nd = min(cnt, KNN);                    // distinct neighbors (>=1: self)
    int basep = 0;
    if (lane == 0) basep = atomicAdd(&g_pcount, nd);
    basep = __shfl_sync(FULLMASK, basep, 0);
    if (lane < nd)
        g_pairs[basep + lane] = ((unsigned)b << 22) | ((unsigned)m << 12) | (unsigned)myn;
}

// --------------------------------------------------------------------------
// Kernel 3: thread-per-distinct-pair fused MLP; max-pool via atomicMax (relu>=0)
// dynamic smem: 48KB exactly (scaled w2T, w3T)
// --------------------------------------------------------------------------
__global__ void __launch_bounds__(256) k_mlp(
    const float* __restrict__ points,
    const float* __restrict__ w1, const float* __restrict__ b1,
    const float* __restrict__ g1, const float* __restrict__ be1,
    const float* __restrict__ w2, const float* __restrict__ b2,
    const float* __restrict__ g2, const float* __restrict__ be2,
    const float* __restrict__ w3, const float* __restrict__ b3,
    const float* __restrict__ g3, const float* __restrict__ be3,
    float* __restrict__ d_out)
{
    const int pcount = g_pcount;
    int i0 = blockIdx.x * 256 + threadIdx.x;
    if (blockIdx.x * 256 >= pcount) return;    // no work for this block at all

    extern __shared__ float smf[];             // [0,4096) w2T*s2 ; [4096,12288) w3T*s3
    const int tid = threadIdx.x;
    const float inv = 1.0f / sqrtf(1.0f + 1e-5f);

    for (int i = tid; i < 4096; i += 256) {
        int o = i & 63, c = i >> 6;
        smf[c * 64 + o] = w2[o * 64 + c] * (__ldg(g2 + o) * inv);
    }
    for (int i = tid; i < 8192; i += 256) {
        int o = i & 127, c = i >> 7;
        smf[4096 + c * 128 + o] = w3[o * 64 + c] * (__ldg(g3 + o) * inv);
    }
    __syncthreads();

    const unsigned sb = (unsigned)__cvta_generic_to_shared(smf);
    float* ofeat = d_out + (size_t)BB * 3 * MM;
    const float* cent = d_out;                 // [B,3,M] written by k1

    for (int i = i0; i < pcount; i += gridDim.x * 256) {
        unsigned pr = g_pairs[i];
        const int b = pr >> 22, m = (pr >> 12) & 1023, n = pr & 4095;

        const float* px = points + (size_t)b * 3 * NN;
        const float lx = px[n]          - cent[(size_t)b * 3 * MM + m];
        const float ly = px[NN + n]     - cent[(size_t)b * 3 * MM + MM + m];
        const float lz = px[2 * NN + n] - cent[(size_t)b * 3 * MM + 2 * MM + m];

        // ---- layer 1 ----
        float h1[64];
        {
            const float4* hp = (const float4*)(g_h1f + ((size_t)b * NN + n) * 64);
#pragma unroll
            for (int q = 0; q < 16; q++) {
                float4 v = hp[q];
                h1[4 * q] = v.x; h1[4 * q + 1] = v.y; h1[4 * q + 2] = v.z; h1[4 * q + 3] = v.w;
            }
#pragma unroll
            for (int o = 0; o < 64; o++) {
                float raw = h1[o]
                          + __ldg(w1 + o * 67)     * lx
                          + __ldg(w1 + o * 67 + 1) * ly
                          + __ldg(w1 + o * 67 + 2) * lz
                          + __ldg(b1 + o);
                float tv = raw * (__ldg(g1 + o) * inv) + __ldg(be1 + o);
                h1[o] = fmaxf(tv, 0.0f);
            }
        }

        // ---- layer 2 (packed f32x2, scaled weights) ----
        u64 acc[32];
#pragma unroll
        for (int k = 0; k < 32; k++) acc[k] = 0ULL;
#pragma unroll
        for (int c = 0; c < 64; c++) {
            u64 vv = pk2(h1[c], h1[c]);
            unsigned addr = sb + c * 256;
#pragma unroll
            for (int k = 0; k < 16; k++) {
                u64 wa, wb; lds128(wa, wb, addr + k * 16);
                acc[2 * k]     = fma2p(wa, vv, acc[2 * k]);
                acc[2 * k + 1] = fma2p(wb, vv, acc[2 * k + 1]);
            }
        }
        float h2[64];
#pragma unroll
        for (int k = 0; k < 32; k++) upk2(acc[k], h2[2 * k], h2[2 * k + 1]);
#pragma unroll
        for (int o = 0; o < 64; o++) {
            float b2f = fmaf(__ldg(b2 + o), __ldg(g2 + o) * inv, __ldg(be2 + o));
            h2[o] = fmaxf(h2[o] + b2f, 0.0f);
        }

        // ---- layer 3 (4 chunks of 32 outputs) + atomic max-pool ----
#pragma unroll
        for (int ch = 0; ch < 4; ch++) {
            u64 a2[16];
#pragma unroll
            for (int k = 0; k < 16; k++) a2[k] = 0ULL;
#pragma unroll
            for (int c = 0; c < 64; c++) {
                u64 vv = pk2(h2[c], h2[c]);
                unsigned addr = sb + 16384 + c * 512 + ch * 128;
#pragma unroll
                for (int k = 0; k < 8; k++) {
                    u64 wa, wb; lds128(wa, wb, addr + k * 16);
                    a2[2 * k]     = fma2p(wa, vv, a2[2 * k]);
                    a2[2 * k + 1] = fma2p(wb, vv, a2[2 * k + 1]);
                }
            }
            float v[32];
#pragma unroll
            for (int k = 0; k < 16; k++) upk2(a2[k], v[2 * k], v[2 * k + 1]);
#pragma unroll
            for (int j = 0; j < 32; j++) {
                const int o = ch * 32 + j;
                float b3f = fmaf(__ldg(b3 + o), __ldg(g3 + o) * inv, __ldg(be3 + o));
                float r = fmaxf(v[j] + b3f, 0.0f);     // relu'd -> >=0, u32-ordered
                atomicMax((unsigned*)&ofeat[((size_t)b * 128 + o) * MM + m],
                          __float_as_uint(r));
            }
        }
    }
}

// --------------------------------------------------------------------------
extern "C" void kernel_launch(void* const* d_in, const int* in_sizes, int n_in,
                              void* d_out, int out_size)
{
    const float* points   = (const float*)d_in[0];
    const float* features = (const float*)d_in[1];
    const float* w1  = (const float*)d_in[2];
    const float* b1  = (const float*)d_in[3];
    const float* g1  = (const float*)d_in[4];
    const float* be1 = (const float*)d_in[5];
    const float* w2  = (const float*)d_in[6];
    const float* b2  = (const float*)d_in[7];
    const float* g2  = (const float*)d_in[8];
    const float* be2 = (const float*)d_in[9];
    const float* w3  = (const float*)d_in[10];
    const float* b3  = (const float*)d_in[11];
    const float* g3  = (const float*)d_in[12];
    const float* be3 = (const float*)d_in[13];
    float* out = (float*)d_out;

    // K1: FPS + h1f + output zero + pair-counter reset
    k_fps_h1f<<<BB + 256, 256, 16384>>>(points, features, w1, out);
    // K2: ball query -> compacted pair list
    k_ballquery<<<dim3(MM / 8, BB), 256, 3 * NN * 4>>>(points);
    // K3: thread-per-pair MLP + atomic max-pool
    k_mlp<<<1024, 256, 12288 * 4>>>(points,
                                    w1, b1, g1, be1,
                                    w2, b2, g2, be2,
                                    w3, b3, g3, be3, out);
}